// round 6
// baseline (speedup 1.0000x reference)
#include <cuda_runtime.h>
#include <math.h>
#include <stdint.h>

// EnhancedFinancialGAT collapse: initial node features are uniform over nodes,
// so GAT attention (softmax weights summing to 1 per dst) aggregates identical
// messages -> each GAT layer == relu(W @ g + b). Whole net = per-item MLP.
//
// R5 -> R6: depth-3 TMA ring (64KB slots), 27 bigger tiles, and 2 items per
// block (weight float4 read once from smem, FMA'd into both items).

#define IN_DIM 64
#define NT 27              // tiles
#define S  3               // ring depth
#define SLOT_FLOATS 16384  // 64KB per slot
#define ACT_STRIDE 704     // per-item: s0[320] s1[256] s2[128]

struct Tile {
    uint8_t  wi;    // weight/bias index
    uint8_t  c4;    // float4 per row
    uint8_t  vin;   // 0: +0 (s0), 1: +320 (s1), 2: +128 (s0 hi half)
    uint8_t  vout;  // 0: +0,      1: +320,      2: +576 (s2)
    uint16_t row0;
    uint16_t rows;  // 32/64/256
    uint16_t voff;
};

__device__ __constant__ Tile g_tiles[NT] = {
    {0, 16, 0, 1, 0, 256, 0},                                     // W_in
    {1, 64, 1, 0,   0, 64,   0}, {1, 64, 1, 0,  64, 64,  64},     // gat0
    {1, 64, 1, 0, 128, 64, 128}, {1, 64, 1, 0, 192, 64, 192},
    {2, 64, 0, 1,   0, 64,   0}, {2, 64, 0, 1,  64, 64,  64},     // gat1
    {2, 64, 0, 1, 128, 64, 128}, {2, 64, 0, 1, 192, 64, 192},
    {3, 64, 1, 0,   0, 64,   0}, {3, 64, 1, 0,  64, 64,  64},     // gat2
    {3, 64, 1, 0, 128, 64, 128}, {3, 64, 1, 0, 192, 64, 192},
    {4, 80, 0, 1,   0, 32,   0}, {4, 80, 0, 1,  32, 32,  32},     // fuse
    {4, 80, 0, 1,  64, 32,  64}, {4, 80, 0, 1,  96, 32,  96},
    {4, 80, 0, 1, 128, 32, 128}, {4, 80, 0, 1, 160, 32, 160},
    {4, 80, 0, 1, 192, 32, 192}, {4, 80, 0, 1, 224, 32, 224},
    {5, 64, 1, 0,   0, 64,   0}, {5, 64, 1, 0,  64, 64,  64},     // p1
    {6, 64, 1, 0,   0, 64, 128}, {6, 64, 1, 0,  64, 64, 192},     // d1
    {7, 32, 0, 2,   0, 64,   0},                                  // p2
    {8, 32, 2, 2,   0, 64,  64},                                  // d2
};

__device__ __forceinline__ uint32_t smem_u32(const void* p) {
    uint32_t a;
    asm("{ .reg .u64 t; cvta.to.shared.u64 t, %1; cvt.u32.u64 %0, t; }"
        : "=r"(a) : "l"(p));
    return a;
}
__device__ __forceinline__ void mbar_init(uint32_t a, uint32_t cnt) {
    asm volatile("mbarrier.init.shared.b64 [%0], %1;" :: "r"(a), "r"(cnt) : "memory");
}
__device__ __forceinline__ void mbar_expect_tx(uint32_t a, uint32_t bytes) {
    asm volatile("mbarrier.arrive.expect_tx.shared.b64 _, [%0], %1;"
                 :: "r"(a), "r"(bytes) : "memory");
}
__device__ __forceinline__ void bulk_g2s(uint32_t dst, const void* src,
                                         uint32_t bytes, uint32_t mbar) {
    asm volatile(
        "cp.async.bulk.shared::cluster.global.mbarrier::complete_tx::bytes "
        "[%0], [%1], %2, [%3];"
        :: "r"(dst), "l"(src), "r"(bytes), "r"(mbar) : "memory");
}
__device__ __forceinline__ void mbar_wait(uint32_t a, uint32_t parity) {
    uint32_t done;
    asm volatile(
        "{\n\t.reg .pred p;\n\t"
        "mbarrier.try_wait.parity.acquire.cta.shared::cta.b64 p, [%1], %2;\n\t"
        "selp.b32 %0, 1, 0, p;\n\t}"
        : "=r"(done) : "r"(a), "r"(parity) : "memory");
    if (!done) {
        asm volatile(
            "{\n\t.reg .pred P1;\n\t"
            "W_%=:\n\t"
            "mbarrier.try_wait.parity.acquire.cta.shared::cta.b64 P1, [%0], %1, 0x989680;\n\t"
            "@P1 bra.uni D_%=;\n\t"
            "bra.uni W_%=;\n\t"
            "D_%=:\n\t}"
            :: "r"(a), "r"(parity) : "memory");
    }
}

extern __shared__ __align__(16) float smem_dyn[];

__global__ __launch_bounds__(1024)
void gat_pipe2_kernel(
    const float* __restrict__ x, const int* __restrict__ company_idx,
    const float* __restrict__ W_in,  const float* __restrict__ b_in,
    const float* __restrict__ gat_W, const float* __restrict__ gat_b,
    const float* __restrict__ emb,
    const float* __restrict__ W_fuse, const float* __restrict__ b_fuse,
    const float* __restrict__ W_p1, const float* __restrict__ b_p1,
    const float* __restrict__ W_p2, const float* __restrict__ b_p2,
    const float* __restrict__ W_p3, const float* __restrict__ b_p3,
    const float* __restrict__ W_d1, const float* __restrict__ b_d1,
    const float* __restrict__ W_d2, const float* __restrict__ b_d2,
    const float* __restrict__ W_d3, const float* __restrict__ b_d3,
    float* __restrict__ out)
{
    float* act = smem_dyn + S * SLOT_FLOATS;           // 2 * 704 floats
    uint64_t* mbar64 = (uint64_t*)(act + 2 * ACT_STRIDE);

    const int tid = threadIdx.x;
    const int b0  = blockIdx.x * 2;

    const float* wp[9] = {W_in, gat_W, gat_W + 65536, gat_W + 131072,
                          W_fuse, W_p1, W_d1, W_p2, W_d2};
    const float* bp[9] = {b_in, gat_b, gat_b + 256, gat_b + 512,
                          b_fuse, b_p1, b_d1, b_p2, b_d2};

    const uint32_t mb_base  = smem_u32(mbar64);
    const uint32_t slot_a   = smem_u32(smem_dyn);

    if (tid < S) mbar_init(mb_base + tid * 8, 1);

    // initial activations: x rows + emb rows for both items
    if (tid < 128) {
        const int it = tid >> 6, c = tid & 63;
        const int bb = b0 + it;
        float* s0 = act + it * ACT_STRIDE;
        s0[c]       = __ldg(&x[bb * IN_DIM + c]);
        s0[256 + c] = __ldg(&emb[__ldg(&company_idx[bb]) * IN_DIM + c]);
    }
    __syncthreads();

    // prologue: issue tiles 0 .. S-2
    if (tid == 0) {
#pragma unroll
        for (int t = 0; t < S - 1; t++) {
            Tile ti = g_tiles[t];
            uint32_t bytes = (uint32_t)ti.rows * ti.c4 * 16;
            mbar_expect_tx(mb_base + t * 8, bytes);
            bulk_g2s(slot_a + t * (SLOT_FLOATS * 4),
                     wp[ti.wi] + (uint32_t)ti.row0 * ti.c4 * 4, bytes,
                     mb_base + t * 8);
        }
    }

    const uint16_t vin_off[3]  = {0, 320, 128};
    const uint16_t vout_off[3] = {0, 320, 576};

    for (int t = 0; t < NT; t++) {
        // issue tile t+S-1 (its slot was consumed at tile t-1, sealed by the
        // __syncthreads at the end of iteration t-1)
        if (tid == 0 && t + S - 1 < NT) {
            const int tn = t + S - 1, s = tn % S;
            Tile ti = g_tiles[tn];
            uint32_t bytes = (uint32_t)ti.rows * ti.c4 * 16;
            mbar_expect_tx(mb_base + s * 8, bytes);
            bulk_g2s(slot_a + s * (SLOT_FLOATS * 4),
                     wp[ti.wi] + (uint32_t)ti.row0 * ti.c4 * 4, bytes,
                     mb_base + s * 8);
        }

        const Tile ti = g_tiles[t];
        const int s = t % S;
        mbar_wait(mb_base + s * 8, (t / S) & 1);

        const int rows = ti.rows;
        const int L    = 1024 / rows;          // 4 / 16 / 32
        const int row  = tid / L;
        const int l    = tid - row * L;
        const int c4   = ti.c4;

        const float4* __restrict__ w4 =
            reinterpret_cast<const float4*>(smem_dyn + s * SLOT_FLOATS) + row * c4;
        const float4* __restrict__ va =
            reinterpret_cast<const float4*>(act + vin_off[ti.vin]);
        const float4* __restrict__ vb =
            reinterpret_cast<const float4*>(act + ACT_STRIDE + vin_off[ti.vin]);

        float p0 = 0.f, p1a = 0.f, p2a = 0.f, p3a = 0.f;
        float q0 = 0.f, q1a = 0.f, q2a = 0.f, q3a = 0.f;
        for (int i = l; i < c4; i += L) {
            float4 w = w4[i];
            float4 u = va[i];
            float4 v = vb[i];
            p0  = fmaf(w.x, u.x, p0);
            p1a = fmaf(w.y, u.y, p1a);
            p2a = fmaf(w.z, u.z, p2a);
            p3a = fmaf(w.w, u.w, p3a);
            q0  = fmaf(w.x, v.x, q0);
            q1a = fmaf(w.y, v.y, q1a);
            q2a = fmaf(w.z, v.z, q2a);
            q3a = fmaf(w.w, v.w, q3a);
        }
        float rp = (p0 + p1a) + (p2a + p3a);
        float rq = (q0 + q1a) + (q2a + q3a);
        for (int o = L >> 1; o; o >>= 1) {
            rp += __shfl_xor_sync(0xffffffffu, rp, o);
            rq += __shfl_xor_sync(0xffffffffu, rq, o);
        }
        if (l == 0) {
            float bias = __ldg(bp[ti.wi] + ti.row0 + row);
            const int oo = vout_off[ti.vout] + ti.voff + row;
            act[oo]              = fmaxf(rp + bias, 0.f);
            act[ACT_STRIDE + oo] = fmaxf(rq + bias, 0.f);
        }
        __syncthreads();
    }

    // heads: warp w handles (item = w>>1, head = w&1)
    const int w = tid >> 5, lane = tid & 31;
    if (w < 4) {
        const int it = w >> 1, head = w & 1;
        const float* s2 = act + it * ACT_STRIDE + 576 + head * 64;
        const float* W  = head ? W_d3 : W_p3;
        float2 wv = __ldg(&reinterpret_cast<const float2*>(W)[lane]);
        float2 vv = reinterpret_cast<const float2*>(s2)[lane];
        float r = fmaf(wv.x, vv.x, wv.y * vv.y);
#pragma unroll
        for (int o = 16; o; o >>= 1) r += __shfl_xor_sync(0xffffffffu, r, o);
        if (lane == 0) {
            const int bb = b0 + it;
            if (head == 0) out[bb] = r + __ldg(b_p3);
            else           out[64 + bb] = 1.f / (1.f + expf(-(r + __ldg(b_d3))));
        }
    }
}

extern "C" void kernel_launch(void* const* d_in, const int* in_sizes, int n_in,
                              void* d_out, int out_size) {
    const float* x      = (const float*)d_in[0];
    const int*   ci     = (const int*)  d_in[1];
    const float* W_in   = (const float*)d_in[4];
    const float* b_in   = (const float*)d_in[5];
    const float* gat_W  = (const float*)d_in[6];
    const float* gat_b  = (const float*)d_in[11];
    const float* emb    = (const float*)d_in[12];
    const float* W_fuse = (const float*)d_in[13];
    const float* b_fuse = (const float*)d_in[14];
    const float* W_p1   = (const float*)d_in[15];
    const float* b_p1   = (const float*)d_in[16];
    const float* W_p2   = (const float*)d_in[17];
    const float* b_p2   = (const float*)d_in[18];
    const float* W_p3   = (const float*)d_in[19];
    const float* b_p3   = (const float*)d_in[20];
    const float* W_d1   = (const float*)d_in[21];
    const float* b_d1   = (const float*)d_in[22];
    const float* W_d2   = (const float*)d_in[23];
    const float* b_d2   = (const float*)d_in[24];
    const float* W_d3   = (const float*)d_in[25];
    const float* b_d3   = (const float*)d_in[26];

    const int B = in_sizes[0] / IN_DIM;  // 64

    const int smem_bytes = S * SLOT_FLOATS * 4 + 2 * ACT_STRIDE * 4 + S * 8 + 16;
    cudaFuncSetAttribute(gat_pipe2_kernel,
                         cudaFuncAttributeMaxDynamicSharedMemorySize, smem_bytes);

    gat_pipe2_kernel<<<B / 2, 1024, smem_bytes>>>(
        x, ci, W_in, b_in, gat_W, gat_b, emb, W_fuse, b_fuse,
        W_p1, b_p1, W_p2, b_p2, W_p3, b_p3,
        W_d1, b_d1, W_d2, b_d2, W_d3, b_d3,
        (float*)d_out);
}